// round 4
// baseline (speedup 1.0000x reference)
#include <cuda_runtime.h>

#define Nn   100000
#define Ee   800000
#define Gg   256

// ---------------- device scratch (no allocations allowed) ----------------
__device__ int   g_flag, g_flag2;         // nonzero => int32 indices
__device__ int   g_src[Ee], g_dst[Ee];
__device__ int   g_batch[Nn];
__device__ int   g_deg[Nn];
__device__ int   g_rowptr[Nn + 1];
__device__ int   g_cursor[Nn];
__device__ int   g_bsum[128];
__device__ int   g_gcount[Gg];
__device__ int   g_gptr[Gg + 1];
__device__ int   g_csr_src[Ee];
__device__ int   g_csr_eid[Ee];
__device__ float g_ae[Ee * 12];           // folded per-edge logits [E][l*4+h]
__device__ float g_mcoef[192];            // [(l*4+h)*16 + j]
__device__ float g_ccoef[12];
__device__ float g_xl[Nn * 128];
__device__ float g_h[Nn * 128];
__device__ float g_agg[Nn * 128];
__device__ float g_as[Nn * 4], g_ad[Nn * 4];
__device__ float g_alpha[Ee * 4];         // post-leaky logits, CSR order
__device__ float g_psum[256 * 128], g_psq[256 * 128];
__device__ float g_bnA[128], g_bnB[128];

// ---------------- setup ----------------
__global__ void zero_kernel() {
    int i = blockIdx.x * blockDim.x + threadIdx.x;
    if (i < Nn) g_deg[i] = 0;
    if (i < Gg) g_gcount[i] = 0;
    if (i == 0) { g_flag = 0; g_flag2 = 0; }
}

// int64 values < 2^31 => every odd 32-bit word is zero. int32 => odd words are
// live indices (virtually surely nonzero somewhere in 256 samples).
__global__ void detect_kernel(const unsigned int* __restrict__ w) {
    if (w[2 * threadIdx.x + 1] != 0u) atomicOr(&g_flag, 1);
}
// batch: probe odd words near index Nn (in-bounds for both dtypes; int32 there
// holds batch[~99500] ~ 255, int64 there holds a high word = 0).
__global__ void detect2_kernel(const unsigned int* __restrict__ w) {
    if (w[Nn - 512 + 2 * threadIdx.x + 1] != 0u) atomicOr(&g_flag2, 1);
}

__global__ void conv_edge_kernel(const void* __restrict__ ei) {
    int e = blockIdx.x * blockDim.x + threadIdx.x;
    if (e >= Ee) return;
    if (g_flag == 0) {
        const long long* p = (const long long*)ei;
        g_src[e] = (int)p[e]; g_dst[e] = (int)p[Ee + e];
    } else {
        const int* p = (const int*)ei;
        g_src[e] = p[e]; g_dst[e] = p[Ee + e];
    }
}

__global__ void conv_batch_kernel(const void* __restrict__ bp) {
    int i = blockIdx.x * blockDim.x + threadIdx.x;
    if (i >= Nn) return;
    g_batch[i] = (g_flag2 == 0) ? (int)((const long long*)bp)[i] : ((const int*)bp)[i];
}

__global__ void hist_kernel() {
    int e = blockIdx.x * blockDim.x + threadIdx.x;
    if (e < Ee) atomicAdd(&g_deg[g_dst[e]], 1);
}
__global__ void bhist_kernel() {
    int i = blockIdx.x * blockDim.x + threadIdx.x;
    if (i < Nn) atomicAdd(&g_gcount[g_batch[i]], 1);
}

__global__ void scan1_kernel() {
    __shared__ int sh[1024];
    int t = threadIdx.x;
    int i = blockIdx.x * 1024 + t;
    int v = (i < Nn) ? g_deg[i] : 0;
    sh[t] = v; __syncthreads();
    for (int off = 1; off < 1024; off <<= 1) {
        int x = (t >= off) ? sh[t - off] : 0;
        __syncthreads(); sh[t] += x; __syncthreads();
    }
    if (i < Nn) g_rowptr[i] = sh[t] - v;
    if (t == 1023) g_bsum[blockIdx.x] = sh[t];
}
__global__ void scan2_kernel() {
    int run = 0;
    for (int b = 0; b < 98; b++) { int x = g_bsum[b]; g_bsum[b] = run; run += x; }
    g_rowptr[Nn] = run;
}
__global__ void scan3_kernel() {
    int i = blockIdx.x * 1024 + threadIdx.x;
    if (i < Nn) {
        int v = g_rowptr[i] + g_bsum[blockIdx.x];
        g_rowptr[i] = v; g_cursor[i] = v;
    }
}
__global__ void bscan_kernel() {
    __shared__ int sh[Gg];
    int t = threadIdx.x;
    int v = g_gcount[t];
    sh[t] = v; __syncthreads();
    for (int off = 1; off < Gg; off <<= 1) {
        int x = (t >= off) ? sh[t - off] : 0;
        __syncthreads(); sh[t] += x; __syncthreads();
    }
    g_gptr[t] = sh[t] - v;
    if (t == Gg - 1) g_gptr[Gg] = sh[t];
}

__global__ void csr_kernel() {
    int e = blockIdx.x * blockDim.x + threadIdx.x;
    if (e >= Ee) return;
    int p = atomicAdd(&g_cursor[g_dst[e]], 1);
    g_csr_src[p] = g_src[e];
    g_csr_eid[p] = e;
}

// fold edge_fc + lin_e + att_edge: alpha_e[e,l,h] = ea[e,:]·m[l,h,:] + c[l,h]
__global__ void prep_kernel(const float* __restrict__ linE, const float* __restrict__ attE,
                            const float* __restrict__ efcW, const float* __restrict__ efcb) {
    __shared__ float wev[384];     // [l][h][k], k<32
    int t = threadIdx.x;
    if (t < 384) {
        int l = t >> 7, hk = t & 127, h = hk >> 5, k = hk & 31;
        float s = 0.f;
        for (int c = 0; c < 32; c++)
            s += linE[l * 4096 + k * 128 + h * 32 + c] * attE[l * 128 + h * 32 + c];
        wev[t] = s;
    }
    __syncthreads();
    if (t < 192) {
        int l = t / 64, r = t % 64, h = r / 16, j = r % 16;
        float s = 0.f;
        for (int k = 0; k < 32; k++) s += efcW[j * 32 + k] * wev[l * 128 + h * 32 + k];
        g_mcoef[t] = s;
    }
    if (t < 12) {
        int l = t >> 2, h = t & 3;
        float s = 0.f;
        for (int k = 0; k < 32; k++) s += efcb[k] * wev[l * 128 + h * 32 + k];
        g_ccoef[t] = s;
    }
}

__global__ void aek_kernel(const float* __restrict__ ea) {
    int e = blockIdx.x * blockDim.x + threadIdx.x;
    if (e >= Ee) return;
    const float4* p = (const float4*)ea + e * 4;
    float4 a0 = p[0], a1 = p[1], a2 = p[2], a3 = p[3];
    float v[16] = {a0.x,a0.y,a0.z,a0.w, a1.x,a1.y,a1.z,a1.w,
                   a2.x,a2.y,a2.z,a2.w, a3.x,a3.y,a3.z,a3.w};
    float o[12];
#pragma unroll
    for (int t = 0; t < 12; t++) {
        float s = g_ccoef[t];
#pragma unroll
        for (int j = 0; j < 16; j++) s = fmaf(v[j], g_mcoef[t * 16 + j], s);
        o[t] = s;
    }
    float4* q = (float4*)&g_ae[e * 12];
    q[0] = make_float4(o[0], o[1], o[2], o[3]);
    q[1] = make_float4(o[4], o[5], o[6], o[7]);
    q[2] = make_float4(o[8], o[9], o[10], o[11]);
}

// ---------------- per-layer ----------------
// xl = A @ W ; A=[Nn,128] (x or g_h), W=[128,128]. BM=64, BK=32, fp32 FMA.
__global__ void __launch_bounds__(256, 2) gemm_kernel(const float* __restrict__ Aext,
                                                      const float* __restrict__ W) {
    __shared__ float As[64][40];
    __shared__ float Bs[32][132];
    const float* A = Aext ? Aext : g_h;
    int tid = threadIdx.x;
    int row0 = blockIdx.x * 64;
    int tx = tid & 31, ty = tid >> 5;
    int n0 = tx * 4, m0 = ty * 8;
    float acc[8][4];
#pragma unroll
    for (int m = 0; m < 8; m++) { acc[m][0]=0.f; acc[m][1]=0.f; acc[m][2]=0.f; acc[m][3]=0.f; }

    for (int kt = 0; kt < 4; kt++) {
        int kb = kt * 32;
#pragma unroll
        for (int i = 0; i < 2; i++) {
            int idx = tid + 256 * i;
            int r = idx >> 3, k4 = idx & 7;
            int gr = row0 + r;
            float4 v = make_float4(0.f, 0.f, 0.f, 0.f);
            if (gr < Nn) v = ((const float4*)A)[gr * 32 + (kb >> 2) + k4];
            *(float4*)&As[r][k4 * 4] = v;
        }
#pragma unroll
        for (int i = 0; i < 4; i++) {
            int idx = tid + 256 * i;
            int r = idx >> 5, c4 = idx & 31;
            float4 v = ((const float4*)W)[(kb + r) * 32 + c4];
            *(float4*)&Bs[r][c4 * 4] = v;
        }
        __syncthreads();
#pragma unroll
        for (int k = 0; k < 32; k++) {
            float4 b = *(const float4*)&Bs[k][n0];
#pragma unroll
            for (int m = 0; m < 8; m++) {
                float av = As[m0 + m][k];
                acc[m][0] = fmaf(av, b.x, acc[m][0]);
                acc[m][1] = fmaf(av, b.y, acc[m][1]);
                acc[m][2] = fmaf(av, b.z, acc[m][2]);
                acc[m][3] = fmaf(av, b.w, acc[m][3]);
            }
        }
        __syncthreads();
    }
#pragma unroll
    for (int m = 0; m < 8; m++) {
        int gr = row0 + m0 + m;
        if (gr < Nn)
            *(float4*)&g_xl[gr * 128 + n0] =
                make_float4(acc[m][0], acc[m][1], acc[m][2], acc[m][3]);
    }
}

// per-node (xl·att_src), (xl·att_dst): one warp per node
__global__ void asad_kernel(const float* __restrict__ attS, const float* __restrict__ attD) {
    int gw = (blockIdx.x * blockDim.x + threadIdx.x) >> 5;
    int lane = threadIdx.x & 31;
    if (gw >= Nn) return;
    float4 v  = ((const float4*)g_xl)[gw * 32 + lane];
    float4 cs = ((const float4*)attS)[lane];
    float4 cd = ((const float4*)attD)[lane];
    float ps = v.x*cs.x + v.y*cs.y + v.z*cs.z + v.w*cs.w;
    float pd = v.x*cd.x + v.y*cd.y + v.z*cd.z + v.w*cd.w;
    ps += __shfl_xor_sync(~0u, ps, 1); pd += __shfl_xor_sync(~0u, pd, 1);
    ps += __shfl_xor_sync(~0u, ps, 2); pd += __shfl_xor_sync(~0u, pd, 2);
    ps += __shfl_xor_sync(~0u, ps, 4); pd += __shfl_xor_sync(~0u, pd, 4);
    if ((lane & 7) == 0) {
        int h = lane >> 3;
        g_as[gw * 4 + h] = ps;
        g_ad[gw * 4 + h] = pd;
    }
}

// one warp per destination node: online softmax + weighted gather, no atomics
__global__ void agg_kernel(int layer, const float* __restrict__ bias) {
    int gw = (blockIdx.x * blockDim.x + threadIdx.x) >> 5;
    int lane = threadIdx.x & 31;
    if (gw >= Nn) return;
    int r0  = g_rowptr[gw];
    int deg = g_rowptr[gw + 1] - r0;
    float4 adv = ((const float4*)g_ad)[gw];

    float mx0=-1e30f, mx1=-1e30f, mx2=-1e30f, mx3=-1e30f;
    float s0=0.f, s1=0.f, s2=0.f, s3=0.f;
    for (int i = lane; i < deg; i += 32) {
        int idx = r0 + i;
        int s   = g_csr_src[idx];
        int eid = g_csr_eid[idx];
        float4 aev = *(const float4*)(g_ae + eid * 12 + layer * 4);
        float4 asv = ((const float4*)g_as)[s];
        float a0 = asv.x + adv.x + aev.x;
        float a1 = asv.y + adv.y + aev.y;
        float a2 = asv.z + adv.z + aev.z;
        float a3 = asv.w + adv.w + aev.w;
        a0 = a0 > 0.f ? a0 : 0.2f * a0;
        a1 = a1 > 0.f ? a1 : 0.2f * a1;
        a2 = a2 > 0.f ? a2 : 0.2f * a2;
        a3 = a3 > 0.f ? a3 : 0.2f * a3;
        ((float4*)g_alpha)[idx] = make_float4(a0, a1, a2, a3);
        float nm;
        nm = fmaxf(mx0, a0); s0 = s0 * __expf(mx0 - nm) + __expf(a0 - nm); mx0 = nm;
        nm = fmaxf(mx1, a1); s1 = s1 * __expf(mx1 - nm) + __expf(a1 - nm); mx1 = nm;
        nm = fmaxf(mx2, a2); s2 = s2 * __expf(mx2 - nm) + __expf(a2 - nm); mx2 = nm;
        nm = fmaxf(mx3, a3); s3 = s3 * __expf(mx3 - nm) + __expf(a3 - nm); mx3 = nm;
    }
    for (int o = 16; o > 0; o >>= 1) {
        float om, os, nm;
        om = __shfl_xor_sync(~0u, mx0, o); os = __shfl_xor_sync(~0u, s0, o);
        nm = fmaxf(mx0, om); s0 = s0 * __expf(mx0 - nm) + os * __expf(om - nm); mx0 = nm;
        om = __shfl_xor_sync(~0u, mx1, o); os = __shfl_xor_sync(~0u, s1, o);
        nm = fmaxf(mx1, om); s1 = s1 * __expf(mx1 - nm) + os * __expf(om - nm); mx1 = nm;
        om = __shfl_xor_sync(~0u, mx2, o); os = __shfl_xor_sync(~0u, s2, o);
        nm = fmaxf(mx2, om); s2 = s2 * __expf(mx2 - nm) + os * __expf(om - nm); mx2 = nm;
        om = __shfl_xor_sync(~0u, mx3, o); os = __shfl_xor_sync(~0u, s3, o);
        nm = fmaxf(mx3, om); s3 = s3 * __expf(mx3 - nm) + os * __expf(om - nm); mx3 = nm;
    }
    __syncwarp();
    int head = lane >> 3;
    float hm = (head == 0) ? mx0 : (head == 1) ? mx1 : (head == 2) ? mx2 : mx3;
    float hs = (head == 0) ? s0  : (head == 1) ? s1  : (head == 2) ? s2  : s3;
    float hinv = 1.f / (hs + 1e-16f);

    float4 acc = make_float4(0.f, 0.f, 0.f, 0.f);
    for (int i = 0; i < deg; i++) {
        int idx = r0 + i;
        int s = g_csr_src[idx];
        float w = __expf(g_alpha[idx * 4 + head] - hm) * hinv;
        float4 v = ((const float4*)g_xl)[s * 32 + lane];
        acc.x = fmaf(w, v.x, acc.x);
        acc.y = fmaf(w, v.y, acc.y);
        acc.z = fmaf(w, v.z, acc.z);
        acc.w = fmaf(w, v.w, acc.w);
    }
    float4 bv = ((const float4*)bias)[lane];
    acc.x += bv.x; acc.y += bv.y; acc.z += bv.z; acc.w += bv.w;
    ((float4*)g_agg)[gw * 32 + lane] = acc;
}

// ---------------- batchnorm (training stats) + relu ----------------
__global__ void bnp_kernel() {
    int c = threadIdx.x, b = blockIdx.x;
    int rs = b * 391, re = rs + 391; if (re > Nn) re = Nn;
    float s = 0.f, q = 0.f;
    for (int r = rs; r < re; r++) {
        float v = g_agg[r * 128 + c];
        s += v; q = fmaf(v, v, q);
    }
    g_psum[b * 128 + c] = s;
    g_psq[b * 128 + c]  = q;
}
__global__ void bnf_kernel(const float* __restrict__ gamma, const float* __restrict__ beta) {
    int c = threadIdx.x;
    float s = 0.f, q = 0.f;
    for (int b = 0; b < 256; b++) { s += g_psum[b * 128 + c]; q += g_psq[b * 128 + c]; }
    float mu  = s * (1.f / Nn);
    float var = q * (1.f / Nn) - mu * mu;
    float A = gamma[c] * rsqrtf(var + 1e-5f);
    g_bnA[c] = A;
    g_bnB[c] = beta[c] - mu * A;
}
__global__ void bna_kernel() {
    int i = blockIdx.x * blockDim.x + threadIdx.x;   // float4 index
    if (i >= Nn * 32) return;
    int c4 = i & 31;
    float4 v = ((const float4*)g_agg)[i];
    float4 A = ((const float4*)g_bnA)[c4];
    float4 B = ((const float4*)g_bnB)[c4];
    float4 o;
    o.x = fmaxf(fmaf(v.x, A.x, B.x), 0.f);
    o.y = fmaxf(fmaf(v.y, A.y, B.y), 0.f);
    o.z = fmaxf(fmaf(v.z, A.z, B.z), 0.f);
    o.w = fmaxf(fmaf(v.w, A.w, B.w), 0.f);
    ((float4*)g_h)[i] = o;
}

// ---------------- pool + FC ----------------
__global__ void pool_kernel(const float* __restrict__ fcW, const float* __restrict__ fcb,
                            float* __restrict__ out) {
    __shared__ float sh0[128], sh1[128];
    int g = blockIdx.x, c = threadIdx.x;
    int rs = g_gptr[g], re = g_gptr[g + 1];
    float s = 0.f;
    for (int r = rs; r < re; r++) s += g_h[r * 128 + c];
    float pooled = s / fmaxf((float)(re - rs), 1.0f);
    sh0[c] = pooled * fcW[c * 2 + 0];
    sh1[c] = pooled * fcW[c * 2 + 1];
    __syncthreads();
    for (int st = 64; st > 0; st >>= 1) {
        if (c < st) { sh0[c] += sh0[c + st]; sh1[c] += sh1[c + st]; }
        __syncthreads();
    }
    if (c == 0) {
        out[g * 2 + 0] = sh0[0] + fcb[0];
        out[g * 2 + 1] = sh1[0] + fcb[1];
    }
}

// ---------------- launcher ----------------
extern "C" void kernel_launch(void* const* d_in, const int* in_sizes, int n_in,
                              void* d_out, int out_size) {
    const float* x      = (const float*)d_in[0];
    const void*  ei     = d_in[1];
    const float* eattr  = (const float*)d_in[2];
    const void*  batchp = d_in[3];
    const float* efcW   = (const float*)d_in[4];
    const float* efcb   = (const float*)d_in[5];
    const float* Ws     = (const float*)d_in[6];
    const float* attS   = (const float*)d_in[7];
    const float* attD   = (const float*)d_in[8];
    const float* attE   = (const float*)d_in[9];
    const float* linE   = (const float*)d_in[10];
    const float* biases = (const float*)d_in[11];
    const float* gamma  = (const float*)d_in[12];
    const float* beta   = (const float*)d_in[13];
    const float* fcW    = (const float*)d_in[14];
    const float* fcb    = (const float*)d_in[15];
    float* out = (float*)d_out;

    zero_kernel<<<391, 256>>>();
    detect_kernel<<<1, 256>>>((const unsigned int*)ei);
    detect2_kernel<<<1, 256>>>((const unsigned int*)batchp);
    conv_edge_kernel<<<3125, 256>>>(ei);
    conv_batch_kernel<<<391, 256>>>(batchp);
    hist_kernel<<<3125, 256>>>();
    bhist_kernel<<<391, 256>>>();
    scan1_kernel<<<98, 1024>>>();
    scan2_kernel<<<1, 1>>>();
    scan3_kernel<<<98, 1024>>>();
    bscan_kernel<<<1, 256>>>();
    csr_kernel<<<3125, 256>>>();
    prep_kernel<<<1, 384>>>(linE, attE, efcW, efcb);
    aek_kernel<<<3125, 256>>>(eattr);

    for (int l = 0; l < 3; l++) {
        gemm_kernel<<<1563, 256>>>(l == 0 ? x : nullptr, Ws + l * 16384);
        asad_kernel<<<12500, 256>>>(attS + l * 128, attD + l * 128);
        agg_kernel<<<12500, 256>>>(l, biases + l * 128);
        bnp_kernel<<<256, 128>>>();
        bnf_kernel<<<1, 128>>>(gamma + l * 128, beta + l * 128);
        bna_kernel<<<12500, 256>>>();
    }
    pool_kernel<<<Gg, 128>>>(fcW, fcb, out);
}

// round 5
// speedup vs baseline: 1.0803x; 1.0803x over previous
#include <cuda_runtime.h>

#define Nn   100000
#define Ee   800000
#define Gg   256

// ---------------- device scratch ----------------
__device__ int   g_flag, g_flag2;
__device__ int   g_src[Ee], g_dst[Ee];
__device__ int   g_batch[Nn];
__device__ int   g_deg[Nn];
__device__ int   g_rowptr[Nn + 1];
__device__ int   g_cursor[Nn];
__device__ int   g_bsum[128];
__device__ int   g_gcount[Gg];
__device__ int   g_gptr[Gg + 1];
__device__ int   g_csr_src[Ee];
__device__ int   g_csr_eid[Ee];
__device__ float g_ae[Ee * 12];
__device__ float g_mcoef[192];
__device__ float g_ccoef[12];
__device__ float g_xl[Nn * 128];
__device__ float g_agg[Nn * 128];
__device__ float g_as[Nn * 4], g_ad[Nn * 4];
__device__ float g_alpha[Ee * 4];
__device__ float g_psum[256 * 128], g_psq[256 * 128];
__device__ float g_bnA[128], g_bnB[128];

// ---------------- helpers ----------------
__device__ __forceinline__ unsigned f2tf(float f) {
    unsigned r; asm("cvt.rna.tf32.f32 %0, %1;" : "=r"(r) : "f"(f)); return r;
}
__device__ __forceinline__ void mma8(float* c, unsigned a0, unsigned a1, unsigned a2,
                                     unsigned a3, unsigned b0, unsigned b1) {
    asm("mma.sync.aligned.m16n8k8.row.col.f32.tf32.tf32.f32 "
        "{%0,%1,%2,%3}, {%4,%5,%6,%7}, {%8,%9}, {%0,%1,%2,%3};"
        : "+f"(c[0]), "+f"(c[1]), "+f"(c[2]), "+f"(c[3])
        : "r"(a0), "r"(a1), "r"(a2), "r"(a3), "r"(b0), "r"(b1));
}

// ---------------- setup ----------------
__global__ void zero_kernel() {
    int i = blockIdx.x * blockDim.x + threadIdx.x;
    if (i < Nn) g_deg[i] = 0;
    if (i < Gg) g_gcount[i] = 0;
    if (i == 0) { g_flag = 0; g_flag2 = 0; }
}
__global__ void detect_kernel(const unsigned int* __restrict__ w) {
    if (w[2 * threadIdx.x + 1] != 0u) atomicOr(&g_flag, 1);
}
__global__ void detect2_kernel(const unsigned int* __restrict__ w) {
    if (w[Nn - 512 + 2 * threadIdx.x + 1] != 0u) atomicOr(&g_flag2, 1);
}
__global__ void conv_edge_kernel(const void* __restrict__ ei) {
    int e = blockIdx.x * blockDim.x + threadIdx.x;
    if (e >= Ee) return;
    int s, d;
    if (g_flag == 0) {
        const long long* p = (const long long*)ei;
        s = (int)p[e]; d = (int)p[Ee + e];
    } else {
        const int* p = (const int*)ei;
        s = p[e]; d = p[Ee + e];
    }
    g_src[e] = s; g_dst[e] = d;
    atomicAdd(&g_deg[d], 1);
}
__global__ void conv_batch_kernel(const void* __restrict__ bp) {
    int i = blockIdx.x * blockDim.x + threadIdx.x;
    if (i >= Nn) return;
    int b = (g_flag2 == 0) ? (int)((const long long*)bp)[i] : ((const int*)bp)[i];
    g_batch[i] = b;
    atomicAdd(&g_gcount[b], 1);
}
__global__ void scan1_kernel() {
    __shared__ int sh[1024];
    int t = threadIdx.x, i = blockIdx.x * 1024 + t;
    int v = (i < Nn) ? g_deg[i] : 0;
    sh[t] = v; __syncthreads();
    for (int off = 1; off < 1024; off <<= 1) {
        int x = (t >= off) ? sh[t - off] : 0;
        __syncthreads(); sh[t] += x; __syncthreads();
    }
    if (i < Nn) g_rowptr[i] = sh[t] - v;
    if (t == 1023) g_bsum[blockIdx.x] = sh[t];
}
__global__ void scan2_kernel() {
    int run = 0;
    for (int b = 0; b < 98; b++) { int x = g_bsum[b]; g_bsum[b] = run; run += x; }
    g_rowptr[Nn] = run;
}
__global__ void scan3_kernel() {
    int i = blockIdx.x * 1024 + threadIdx.x;
    if (i < Nn) {
        int v = g_rowptr[i] + g_bsum[blockIdx.x];
        g_rowptr[i] = v; g_cursor[i] = v;
    }
}
__global__ void bscan_kernel() {
    __shared__ int sh[Gg];
    int t = threadIdx.x, v = g_gcount[t];
    sh[t] = v; __syncthreads();
    for (int off = 1; off < Gg; off <<= 1) {
        int x = (t >= off) ? sh[t - off] : 0;
        __syncthreads(); sh[t] += x; __syncthreads();
    }
    g_gptr[t] = sh[t] - v;
    if (t == Gg - 1) g_gptr[Gg] = sh[t];
}
__global__ void csr_kernel() {
    int e = blockIdx.x * blockDim.x + threadIdx.x;
    if (e >= Ee) return;
    int p = atomicAdd(&g_cursor[g_dst[e]], 1);
    g_csr_src[p] = g_src[e];
    g_csr_eid[p] = e;
}

__global__ void prep_kernel(const float* __restrict__ linE, const float* __restrict__ attE,
                            const float* __restrict__ efcW, const float* __restrict__ efcb) {
    __shared__ float wev[384];
    int t = threadIdx.x;
    if (t < 384) {
        int l = t >> 7, hk = t & 127, h = hk >> 5, k = hk & 31;
        float s = 0.f;
        for (int c = 0; c < 32; c++)
            s += linE[l * 4096 + k * 128 + h * 32 + c] * attE[l * 128 + h * 32 + c];
        wev[t] = s;
    }
    __syncthreads();
    if (t < 192) {
        int l = t / 64, r = t % 64, h = r / 16, j = r % 16;
        float s = 0.f;
        for (int k = 0; k < 32; k++) s += efcW[j * 32 + k] * wev[l * 128 + h * 32 + k];
        g_mcoef[t] = s;
    }
    if (t < 12) {
        int l = t >> 2, h = t & 3;
        float s = 0.f;
        for (int k = 0; k < 32; k++) s += efcb[k] * wev[l * 128 + h * 32 + k];
        g_ccoef[t] = s;
    }
}

__global__ void aek_kernel(const float* __restrict__ ea) {
    int e = blockIdx.x * blockDim.x + threadIdx.x;
    if (e >= Ee) return;
    const float4* p = (const float4*)ea + e * 4;
    float4 a0 = p[0], a1 = p[1], a2 = p[2], a3 = p[3];
    float v[16] = {a0.x,a0.y,a0.z,a0.w, a1.x,a1.y,a1.z,a1.w,
                   a2.x,a2.y,a2.z,a2.w, a3.x,a3.y,a3.z,a3.w};
    float o[12];
#pragma unroll
    for (int t = 0; t < 12; t++) {
        float s = g_ccoef[t];
#pragma unroll
        for (int j = 0; j < 16; j++) s = fmaf(v[j], g_mcoef[t * 16 + j], s);
        o[t] = s;
    }
    float4* q = (float4*)&g_ae[e * 12];
    q[0] = make_float4(o[0], o[1], o[2], o[3]);
    q[1] = make_float4(o[4], o[5], o[6], o[7]);
    q[2] = make_float4(o[8], o[9], o[10], o[11]);
}

// ---------------- tensor-core GEMM (3xTF32) + fused BN/ReLU + fused asad ----------------
__global__ void __launch_bounds__(256, 2) gemm_tc(const float* __restrict__ Aext,
                                                  const float* __restrict__ W,
                                                  int doBN,
                                                  const float* __restrict__ attS,
                                                  const float* __restrict__ attD) {
    __shared__ unsigned Wh[32][136];
    __shared__ unsigned Wl[32][136];
    __shared__ float sAtt[256];
    __shared__ float sBnA[128], sBnB[128];

    const float* A = doBN ? (const float*)g_agg : Aext;
    int tid = threadIdx.x;
    if (tid < 128) { sAtt[tid] = attS[tid]; sAtt[128 + tid] = attD[tid]; }
    if (tid < 128) {
        sBnA[tid] = doBN ? g_bnA[tid] : 1.f;
        sBnB[tid] = doBN ? g_bnB[tid] : 0.f;
    }

    int w = tid >> 5, lane = tid & 31;
    int grp = lane >> 2, q = lane & 3;
    int row0 = blockIdx.x * 128;
    int r0 = row0 + w * 16 + grp;
    int r1 = r0 + 8;

    float acc[16][4];
#pragma unroll
    for (int nt = 0; nt < 16; nt++) { acc[nt][0]=0.f; acc[nt][1]=0.f; acc[nt][2]=0.f; acc[nt][3]=0.f; }

    for (int kb = 0; kb < 128; kb += 32) {
        __syncthreads();
#pragma unroll
        for (int i = 0; i < 16; i++) {
            int idx = tid + 256 * i;
            int r = idx >> 7, c = idx & 127;
            float v = W[(kb + r) * 128 + c];
            unsigned hi = f2tf(v);
            Wh[r][c] = hi;
            Wl[r][c] = f2tf(v - __uint_as_float(hi));
        }
        __syncthreads();
#pragma unroll
        for (int s = 0; s < 4; s++) {
            int c0 = kb + s * 8 + q;
            int c1 = c0 + 4;
            float a00 = 0.f, a10 = 0.f, a01 = 0.f, a11 = 0.f;
            if (r0 < Nn) { a00 = A[r0 * 128 + c0]; a01 = A[r0 * 128 + c1]; }
            if (r1 < Nn) { a10 = A[r1 * 128 + c0]; a11 = A[r1 * 128 + c1]; }
            if (doBN) {
                a00 = fmaxf(fmaf(a00, sBnA[c0], sBnB[c0]), 0.f);
                a10 = fmaxf(fmaf(a10, sBnA[c0], sBnB[c0]), 0.f);
                a01 = fmaxf(fmaf(a01, sBnA[c1], sBnB[c1]), 0.f);
                a11 = fmaxf(fmaf(a11, sBnA[c1], sBnB[c1]), 0.f);
            }
            unsigned h0 = f2tf(a00), h1 = f2tf(a10), h2 = f2tf(a01), h3 = f2tf(a11);
            unsigned l0 = f2tf(a00 - __uint_as_float(h0));
            unsigned l1 = f2tf(a10 - __uint_as_float(h1));
            unsigned l2 = f2tf(a01 - __uint_as_float(h2));
            unsigned l3 = f2tf(a11 - __uint_as_float(h3));
            int kr0 = s * 8 + q, kr1 = kr0 + 4;
#pragma unroll
            for (int nt = 0; nt < 16; nt++) {
                int cn = nt * 8 + grp;
                unsigned b0h = Wh[kr0][cn], b1h = Wh[kr1][cn];
                unsigned b0l = Wl[kr0][cn], b1l = Wl[kr1][cn];
                mma8(acc[nt], h0, h1, h2, h3, b0h, b1h);
                mma8(acc[nt], h0, h1, h2, h3, b0l, b1l);
                mma8(acc[nt], l0, l1, l2, l3, b0h, b1h);
            }
        }
    }

    float ps0[4] = {0,0,0,0}, pd0[4] = {0,0,0,0}, ps1[4] = {0,0,0,0}, pd1[4] = {0,0,0,0};
#pragma unroll
    for (int nt = 0; nt < 16; nt++) {
        int c0 = nt * 8 + q * 2, c1 = c0 + 1;
        if (r0 < Nn) *(float2*)&g_xl[r0 * 128 + c0] = make_float2(acc[nt][0], acc[nt][1]);
        if (r1 < Nn) *(float2*)&g_xl[r1 * 128 + c0] = make_float2(acc[nt][2], acc[nt][3]);
        int h = nt >> 2;
        ps0[h] += acc[nt][0] * sAtt[c0] + acc[nt][1] * sAtt[c1];
        pd0[h] += acc[nt][0] * sAtt[128 + c0] + acc[nt][1] * sAtt[128 + c1];
        ps1[h] += acc[nt][2] * sAtt[c0] + acc[nt][3] * sAtt[c1];
        pd1[h] += acc[nt][2] * sAtt[128 + c0] + acc[nt][3] * sAtt[128 + c1];
    }
#pragma unroll
    for (int h = 0; h < 4; h++) {
        ps0[h] += __shfl_xor_sync(~0u, ps0[h], 1); ps0[h] += __shfl_xor_sync(~0u, ps0[h], 2);
        pd0[h] += __shfl_xor_sync(~0u, pd0[h], 1); pd0[h] += __shfl_xor_sync(~0u, pd0[h], 2);
        ps1[h] += __shfl_xor_sync(~0u, ps1[h], 1); ps1[h] += __shfl_xor_sync(~0u, ps1[h], 2);
        pd1[h] += __shfl_xor_sync(~0u, pd1[h], 1); pd1[h] += __shfl_xor_sync(~0u, pd1[h], 2);
    }
    if (q == 0) {
#pragma unroll
        for (int h = 0; h < 4; h++) {
            if (r0 < Nn) { g_as[r0 * 4 + h] = ps0[h]; g_ad[r0 * 4 + h] = pd0[h]; }
            if (r1 < Nn) { g_as[r1 * 4 + h] = ps1[h]; g_ad[r1 * 4 + h] = pd1[h]; }
        }
    }
}

// ---------------- attention aggregate ----------------
__global__ void agg_kernel(int layer, const float* __restrict__ bias) {
    int gw = (blockIdx.x * blockDim.x + threadIdx.x) >> 5;
    int lane = threadIdx.x & 31;
    if (gw >= Nn) return;
    int r0  = g_rowptr[gw];
    int deg = g_rowptr[gw + 1] - r0;
    float4 adv = ((const float4*)g_ad)[gw];

    float mx0=-1e30f, mx1=-1e30f, mx2=-1e30f, mx3=-1e30f;
    float s0=0.f, s1=0.f, s2=0.f, s3=0.f;
    for (int i = lane; i < deg; i += 32) {
        int idx = r0 + i;
        int s   = g_csr_src[idx];
        int eid = g_csr_eid[idx];
        float4 aev = *(const float4*)(g_ae + eid * 12 + layer * 4);
        float4 asv = ((const float4*)g_as)[s];
        float a0 = asv.x + adv.x + aev.x;
        float a1 = asv.y + adv.y + aev.y;
        float a2 = asv.z + adv.z + aev.z;
        float a3 = asv.w + adv.w + aev.w;
        a0 = a0 > 0.f ? a0 : 0.2f * a0;
        a1 = a1 > 0.f ? a1 : 0.2f * a1;
        a2 = a2 > 0.f ? a2 : 0.2f * a2;
        a3 = a3 > 0.f ? a3 : 0.2f * a3;
        ((float4*)g_alpha)[idx] = make_float4(a0, a1, a2, a3);
        float nm;
        nm = fmaxf(mx0, a0); s0 = s0 * __expf(mx0 - nm) + __expf(a0 - nm); mx0 = nm;
        nm = fmaxf(mx1, a1); s1 = s1 * __expf(mx1 - nm) + __expf(a1 - nm); mx1 = nm;
        nm = fmaxf(mx2, a2); s2 = s2 * __expf(mx2 - nm) + __expf(a2 - nm); mx2 = nm;
        nm = fmaxf(mx3, a3); s3 = s3 * __expf(mx3 - nm) + __expf(a3 - nm); mx3 = nm;
    }
    for (int o = 16; o > 0; o >>= 1) {
        float om, os, nm;
        om = __shfl_xor_sync(~0u, mx0, o); os = __shfl_xor_sync(~0u, s0, o);
        nm = fmaxf(mx0, om); s0 = s0 * __expf(mx0 - nm) + os * __expf(om - nm); mx0 = nm;
        om = __shfl_xor_sync(~0u, mx1, o); os = __shfl_xor_sync(~0u, s1, o);
        nm = fmaxf(mx1, om); s1 = s1 * __expf(mx1 - nm) + os * __expf(om - nm); mx1 = nm;
        om = __shfl_xor_sync(~0u, mx2, o); os = __shfl_xor_sync(~0u, s2, o);
        nm = fmaxf(mx2, om); s2 = s2 * __expf(mx2 - nm) + os * __expf(om - nm); mx2 = nm;
        om = __shfl_xor_sync(~0u, mx3, o); os = __shfl_xor_sync(~0u, s3, o);
        nm = fmaxf(mx3, om); s3 = s3 * __expf(mx3 - nm) + os * __expf(om - nm); mx3 = nm;
    }
    __syncwarp();
    int head = lane >> 3;
    float hm = (head == 0) ? mx0 : (head == 1) ? mx1 : (head == 2) ? mx2 : mx3;
    float hs = (head == 0) ? s0  : (head == 1) ? s1  : (head == 2) ? s2  : s3;
    float hinv = 1.f / (hs + 1e-16f);

    float4 acc = make_float4(0.f, 0.f, 0.f, 0.f);
    for (int i = 0; i < deg; i++) {
        int idx = r0 + i;
        int s = g_csr_src[idx];
        float wgt = __expf(g_alpha[idx * 4 + head] - hm) * hinv;
        float4 v = ((const float4*)g_xl)[s * 32 + lane];
        acc.x = fmaf(wgt, v.x, acc.x);
        acc.y = fmaf(wgt, v.y, acc.y);
        acc.z = fmaf(wgt, v.z, acc.z);
        acc.w = fmaf(wgt, v.w, acc.w);
    }
    float4 bv = ((const float4*)bias)[lane];
    acc.x += bv.x; acc.y += bv.y; acc.z += bv.z; acc.w += bv.w;
    ((float4*)g_agg)[gw * 32 + lane] = acc;
}

// ---------------- batchnorm stats ----------------
__global__ void bnp_kernel() {
    int c = threadIdx.x, b = blockIdx.x;
    int rs = b * 391, re = rs + 391; if (re > Nn) re = Nn;
    float s = 0.f, q = 0.f;
    for (int r = rs; r < re; r++) {
        float v = g_agg[r * 128 + c];
        s += v; q = fmaf(v, v, q);
    }
    g_psum[b * 128 + c] = s;
    g_psq[b * 128 + c]  = q;
}
__global__ void bnf_kernel(const float* __restrict__ gamma, const float* __restrict__ beta) {
    int c = threadIdx.x;
    float s = 0.f, q = 0.f;
    for (int b = 0; b < 256; b++) { s += g_psum[b * 128 + c]; q += g_psq[b * 128 + c]; }
    float mu  = s * (1.f / Nn);
    float var = q * (1.f / Nn) - mu * mu;
    float A = gamma[c] * rsqrtf(var + 1e-5f);
    g_bnA[c] = A;
    g_bnB[c] = beta[c] - mu * A;
}

// ---------------- pool (+fused last-layer BN/ReLU) + FC ----------------
__global__ void pool_kernel(const float* __restrict__ fcW, const float* __restrict__ fcb,
                            float* __restrict__ out) {
    __shared__ float sh0[128], sh1[128];
    int g = blockIdx.x, c = threadIdx.x;
    int rs = g_gptr[g], re = g_gptr[g + 1];
    float A = g_bnA[c], B = g_bnB[c];
    float s = 0.f;
    for (int r = rs; r < re; r++)
        s += fmaxf(fmaf(g_agg[r * 128 + c], A, B), 0.f);
    float pooled = s / fmaxf((float)(re - rs), 1.0f);
    sh0[c] = pooled * fcW[c * 2 + 0];
    sh1[c] = pooled * fcW[c * 2 + 1];
    __syncthreads();
    for (int st = 64; st > 0; st >>= 1) {
        if (c < st) { sh0[c] += sh0[c + st]; sh1[c] += sh1[c + st]; }
        __syncthreads();
    }
    if (c == 0) {
        out[g * 2 + 0] = sh0[0] + fcb[0];
        out[g * 2 + 1] = sh1[0] + fcb[1];
    }
}

// ---------------- launcher ----------------
extern "C" void kernel_launch(void* const* d_in, const int* in_sizes, int n_in,
                              void* d_out, int out_size) {
    const float* x      = (const float*)d_in[0];
    const void*  ei     = d_in[1];
    const float* eattr  = (const float*)d_in[2];
    const void*  batchp = d_in[3];
    const float* efcW   = (const float*)d_in[4];
    const float* efcb   = (const float*)d_in[5];
    const float* Ws     = (const float*)d_in[6];
    const float* attS   = (const float*)d_in[7];
    const float* attD   = (const float*)d_in[8];
    const float* attE   = (const float*)d_in[9];
    const float* linE   = (const float*)d_in[10];
    const float* biases = (const float*)d_in[11];
    const float* gamma  = (const float*)d_in[12];
    const float* beta   = (const float*)d_in[13];
    const float* fcW    = (const float*)d_in[14];
    const float* fcb    = (const float*)d_in[15];
    float* out = (float*)d_out;

    zero_kernel<<<391, 256>>>();
    detect_kernel<<<1, 256>>>((const unsigned int*)ei);
    detect2_kernel<<<1, 256>>>((const unsigned int*)batchp);
    conv_edge_kernel<<<3125, 256>>>(ei);
    conv_batch_kernel<<<391, 256>>>(batchp);
    scan1_kernel<<<98, 1024>>>();
    scan2_kernel<<<1, 1>>>();
    scan3_kernel<<<98, 1024>>>();
    bscan_kernel<<<1, 256>>>();
    csr_kernel<<<3125, 256>>>();
    prep_kernel<<<1, 384>>>(linE, attE, efcW, efcb);
    aek_kernel<<<3125, 256>>>(eattr);

    for (int l = 0; l < 3; l++) {
        gemm_tc<<<782, 256>>>(x, Ws + l * 16384, l > 0, attS + l * 128, attD + l * 128);
        agg_kernel<<<12500, 256>>>(l, biases + l * 128);
        bnp_kernel<<<256, 128>>>();
        bnf_kernel<<<1, 128>>>(gamma + l * 128, beta + l * 128);
    }
    pool_kernel<<<Gg, 128>>>(fcW, fcb, out);
}

// round 8
// speedup vs baseline: 1.1494x; 1.0640x over previous
#include <cuda_runtime.h>

#define Nn   100000
#define Ee   800000
#define Gg   256

// ---------------- device scratch ----------------
__device__ int   g_flag, g_flag2;
__device__ int   g_src[Ee], g_dst[Ee];
__device__ int   g_batch[Nn];
__device__ int   g_deg[Nn];
__device__ int   g_rowptr[Nn + 1];
__device__ int   g_cursor[Nn];
__device__ int   g_bsum[128];
__device__ int   g_gcount[Gg];
__device__ int   g_gptr[Gg + 1];
__device__ int   g_csr_src[Ee];
__device__ int   g_pos[Ee];               // edge -> CSR slot
__device__ float g_ae[3 * Ee * 4];        // CSR-ordered folded logits, per layer
__device__ float g_mcoef[192];
__device__ float g_ccoef[12];
__device__ float g_xl[Nn * 128];
__device__ float g_agg[Nn * 128];
__device__ float g_as[Nn * 4], g_ad[Nn * 4];
__device__ float g_w[Ee * 4];             // exp(logit), CSR order
__device__ float g_psum[256 * 128], g_psq[256 * 128];
__device__ float g_bnA[128], g_bnB[128];

// ---------------- helpers ----------------
__device__ __forceinline__ unsigned f2tf(float f) {
    unsigned r; asm("cvt.rna.tf32.f32 %0, %1;" : "=r"(r) : "f"(f)); return r;
}
__device__ __forceinline__ void mma8(float* c, unsigned a0, unsigned a1, unsigned a2,
                                     unsigned a3, unsigned b0, unsigned b1) {
    asm("mma.sync.aligned.m16n8k8.row.col.f32.tf32.tf32.f32 "
        "{%0,%1,%2,%3}, {%4,%5,%6,%7}, {%8,%9}, {%0,%1,%2,%3};"
        : "+f"(c[0]), "+f"(c[1]), "+f"(c[2]), "+f"(c[3])
        : "r"(a0), "r"(a1), "r"(a2), "r"(a3), "r"(b0), "r"(b1));
}

// ---------------- setup ----------------
__global__ void zero_kernel() {
    int i = blockIdx.x * blockDim.x + threadIdx.x;
    if (i < Nn) g_deg[i] = 0;
    if (i < Gg) g_gcount[i] = 0;
    if (i == 0) { g_flag = 0; g_flag2 = 0; }
}
__global__ void detect_kernel(const unsigned int* __restrict__ w) {
    if (w[2 * threadIdx.x + 1] != 0u) atomicOr(&g_flag, 1);
}
__global__ void detect2_kernel(const unsigned int* __restrict__ w) {
    if (w[Nn - 512 + 2 * threadIdx.x + 1] != 0u) atomicOr(&g_flag2, 1);
}
__global__ void conv_edge_kernel(const void* __restrict__ ei) {
    int e = blockIdx.x * blockDim.x + threadIdx.x;
    if (e >= Ee) return;
    int s, d;
    if (g_flag == 0) {
        const long long* p = (const long long*)ei;
        s = (int)p[e]; d = (int)p[Ee + e];
    } else {
        const int* p = (const int*)ei;
        s = p[e]; d = p[Ee + e];
    }
    g_src[e] = s; g_dst[e] = d;
    atomicAdd(&g_deg[d], 1);
}
__global__ void conv_batch_kernel(const void* __restrict__ bp) {
    int i = blockIdx.x * blockDim.x + threadIdx.x;
    if (i >= Nn) return;
    int b = (g_flag2 == 0) ? (int)((const long long*)bp)[i] : ((const int*)bp)[i];
    g_batch[i] = b;
    atomicAdd(&g_gcount[b], 1);
}
__global__ void scan1_kernel() {
    __shared__ int sh[1024];
    int t = threadIdx.x, i = blockIdx.x * 1024 + t;
    int v = (i < Nn) ? g_deg[i] : 0;
    sh[t] = v; __syncthreads();
    for (int off = 1; off < 1024; off <<= 1) {
        int x = (t >= off) ? sh[t - off] : 0;
        __syncthreads(); sh[t] += x; __syncthreads();
    }
    if (i < Nn) g_rowptr[i] = sh[t] - v;
    if (t == 1023) g_bsum[blockIdx.x] = sh[t];
}
__global__ void scan2_kernel() {
    int run = 0;
    for (int b = 0; b < 98; b++) { int x = g_bsum[b]; g_bsum[b] = run; run += x; }
    g_rowptr[Nn] = run;
}
__global__ void scan3_kernel() {
    int i = blockIdx.x * 1024 + threadIdx.x;
    if (i < Nn) {
        int v = g_rowptr[i] + g_bsum[blockIdx.x];
        g_rowptr[i] = v; g_cursor[i] = v;
    }
}
__global__ void bscan_kernel() {
    __shared__ int sh[Gg];
    int t = threadIdx.x, v = g_gcount[t];
    sh[t] = v; __syncthreads();
    for (int off = 1; off < Gg; off <<= 1) {
        int x = (t >= off) ? sh[t - off] : 0;
        __syncthreads(); sh[t] += x; __syncthreads();
    }
    g_gptr[t] = sh[t] - v;
    if (t == Gg - 1) g_gptr[Gg] = sh[t];
}
__global__ void csr_kernel() {
    int e = blockIdx.x * blockDim.x + threadIdx.x;
    if (e >= Ee) return;
    int p = atomicAdd(&g_cursor[g_dst[e]], 1);
    g_csr_src[p] = g_src[e];
    g_pos[e] = p;
}

__global__ void prep_kernel(const float* __restrict__ linE, const float* __restrict__ attE,
                            const float* __restrict__ efcW, const float* __restrict__ efcb) {
    __shared__ float wev[384];
    int t = threadIdx.x;
    if (t < 384) {
        int l = t >> 7, hk = t & 127, h = hk >> 5, k = hk & 31;
        float s = 0.f;
        for (int c = 0; c < 32; c++)
            s += linE[l * 4096 + k * 128 + h * 32 + c] * attE[l * 128 + h * 32 + c];
        wev[t] = s;
    }
    __syncthreads();
    if (t < 192) {
        int l = t / 64, r = t % 64, h = r / 16, j = r % 16;
        float s = 0.f;
        for (int k = 0; k < 32; k++) s += efcW[j * 32 + k] * wev[l * 128 + h * 32 + k];
        g_mcoef[t] = s;
    }
    if (t < 12) {
        int l = t >> 2, h = t & 3;
        float s = 0.f;
        for (int k = 0; k < 32; k++) s += efcb[k] * wev[l * 128 + h * 32 + k];
        g_ccoef[t] = s;
    }
}

// folded edge logits, written straight into CSR slots (per-layer contiguous)
__global__ void aek_kernel(const float* __restrict__ ea) {
    int e = blockIdx.x * blockDim.x + threadIdx.x;
    if (e >= Ee) return;
    const float4* p = (const float4*)ea + e * 4;
    float4 a0 = p[0], a1 = p[1], a2 = p[2], a3 = p[3];
    float v[16] = {a0.x,a0.y,a0.z,a0.w, a1.x,a1.y,a1.z,a1.w,
                   a2.x,a2.y,a2.z,a2.w, a3.x,a3.y,a3.z,a3.w};
    float o[12];
#pragma unroll
    for (int t = 0; t < 12; t++) {
        float s = g_ccoef[t];
#pragma unroll
        for (int j = 0; j < 16; j++) s = fmaf(v[j], g_mcoef[t * 16 + j], s);
        o[t] = s;
    }
    int pos = g_pos[e];
    ((float4*)g_ae)[0 * Ee + pos] = make_float4(o[0], o[1], o[2],  o[3]);
    ((float4*)g_ae)[1 * Ee + pos] = make_float4(o[4], o[5], o[6],  o[7]);
    ((float4*)g_ae)[2 * Ee + pos] = make_float4(o[8], o[9], o[10], o[11]);
}

// ---------------- tensor-core GEMM (3xTF32) + fused BN/ReLU + fused asad ----------------
__global__ void __launch_bounds__(256, 2) gemm_tc(const float* __restrict__ Aext,
                                                  const float* __restrict__ W,
                                                  int doBN,
                                                  const float* __restrict__ attS,
                                                  const float* __restrict__ attD) {
    __shared__ unsigned Wh[32][136];
    __shared__ unsigned Wl[32][136];
    __shared__ float sAtt[256];
    __shared__ float sBnA[128], sBnB[128];

    const float* A = doBN ? (const float*)g_agg : Aext;
    int tid = threadIdx.x;
    if (tid < 128) { sAtt[tid] = attS[tid]; sAtt[128 + tid] = attD[tid]; }
    if (tid < 128) {
        sBnA[tid] = doBN ? g_bnA[tid] : 1.f;
        sBnB[tid] = doBN ? g_bnB[tid] : 0.f;
    }

    int w = tid >> 5, lane = tid & 31;
    int grp = lane >> 2, q = lane & 3;
    int row0 = blockIdx.x * 128;
    int r0 = row0 + w * 16 + grp;
    int r1 = r0 + 8;

    float acc[16][4];
#pragma unroll
    for (int nt = 0; nt < 16; nt++) { acc[nt][0]=0.f; acc[nt][1]=0.f; acc[nt][2]=0.f; acc[nt][3]=0.f; }

    for (int kb = 0; kb < 128; kb += 32) {
        __syncthreads();
#pragma unroll
        for (int i = 0; i < 16; i++) {
            int idx = tid + 256 * i;
            int r = idx >> 7, c = idx & 127;
            float v = W[(kb + r) * 128 + c];
            unsigned hi = f2tf(v);
            Wh[r][c] = hi;
            Wl[r][c] = f2tf(v - __uint_as_float(hi));
        }
        __syncthreads();
#pragma unroll
        for (int s = 0; s < 4; s++) {
            int c0 = kb + s * 8 + q;
            int c1 = c0 + 4;
            float a00 = 0.f, a10 = 0.f, a01 = 0.f, a11 = 0.f;
            if (r0 < Nn) { a00 = A[r0 * 128 + c0]; a01 = A[r0 * 128 + c1]; }
            if (r1 < Nn) { a10 = A[r1 * 128 + c0]; a11 = A[r1 * 128 + c1]; }
            if (doBN) {
                a00 = fmaxf(fmaf(a00, sBnA[c0], sBnB[c0]), 0.f);
                a10 = fmaxf(fmaf(a10, sBnA[c0], sBnB[c0]), 0.f);
                a01 = fmaxf(fmaf(a01, sBnA[c1], sBnB[c1]), 0.f);
                a11 = fmaxf(fmaf(a11, sBnA[c1], sBnB[c1]), 0.f);
            }
            unsigned h0 = f2tf(a00), h1 = f2tf(a10), h2 = f2tf(a01), h3 = f2tf(a11);
            unsigned l0 = f2tf(a00 - __uint_as_float(h0));
            unsigned l1 = f2tf(a10 - __uint_as_float(h1));
            unsigned l2 = f2tf(a01 - __uint_as_float(h2));
            unsigned l3 = f2tf(a11 - __uint_as_float(h3));
            int kr0 = s * 8 + q, kr1 = kr0 + 4;
#pragma unroll
            for (int nt = 0; nt < 16; nt++) {
                int cn = nt * 8 + grp;
                unsigned b0h = Wh[kr0][cn], b1h = Wh[kr1][cn];
                unsigned b0l = Wl[kr0][cn], b1l = Wl[kr1][cn];
                mma8(acc[nt], h0, h1, h2, h3, b0h, b1h);
                mma8(acc[nt], h0, h1, h2, h3, b0l, b1l);
                mma8(acc[nt], l0, l1, l2, l3, b0h, b1h);
            }
        }
    }

    float ps0[4] = {0,0,0,0}, pd0[4] = {0,0,0,0}, ps1[4] = {0,0,0,0}, pd1[4] = {0,0,0,0};
#pragma unroll
    for (int nt = 0; nt < 16; nt++) {
        int c0 = nt * 8 + q * 2, c1 = c0 + 1;
        if (r0 < Nn) *(float2*)&g_xl[r0 * 128 + c0] = make_float2(acc[nt][0], acc[nt][1]);
        if (r1 < Nn) *(float2*)&g_xl[r1 * 128 + c0] = make_float2(acc[nt][2], acc[nt][3]);
        int h = nt >> 2;
        ps0[h] += acc[nt][0] * sAtt[c0] + acc[nt][1] * sAtt[c1];
        pd0[h] += acc[nt][0] * sAtt[128 + c0] + acc[nt][1] * sAtt[128 + c1];
        ps1[h] += acc[nt][2] * sAtt[c0] + acc[nt][3] * sAtt[c1];
        pd1[h] += acc[nt][2] * sAtt[128 + c0] + acc[nt][3] * sAtt[128 + c1];
    }
#pragma unroll
    for (int h = 0; h < 4; h++) {
        ps0[h] += __shfl_xor_sync(~0u, ps0[h], 1); ps0[h] += __shfl_xor_sync(~0u, ps0[h], 2);
        pd0[h] += __shfl_xor_sync(~0u, pd0[h], 1); pd0[h] += __shfl_xor_sync(~0u, pd0[h], 2);
        ps1[h] += __shfl_xor_sync(~0u, ps1[h], 1); ps1[h] += __shfl_xor_sync(~0u, ps1[h], 2);
        pd1[h] += __shfl_xor_sync(~0u, pd1[h], 1); pd1[h] += __shfl_xor_sync(~0u, pd1[h], 2);
    }
    if (q == 0) {
#pragma unroll
        for (int h = 0; h < 4; h++) {
            if (r0 < Nn) { g_as[r0 * 4 + h] = ps0[h]; g_ad[r0 * 4 + h] = pd0[h]; }
            if (r1 < Nn) { g_as[r1 * 4 + h] = ps1[h]; g_ad[r1 * 4 + h] = pd1[h]; }
        }
    }
}

// ---------------- attention aggregate: warp per node, no max-subtraction ----------------
__global__ void agg_kernel(int layer, const float* __restrict__ bias) {
    int gw = (blockIdx.x * blockDim.x + threadIdx.x) >> 5;
    int lane = threadIdx.x & 31;
    if (gw >= Nn) return;
    int r0  = g_rowptr[gw];
    int deg = g_rowptr[gw + 1] - r0;
    float4 adv = ((const float4*)g_ad)[gw];
    const float4* aeL = (const float4*)g_ae + layer * Ee;

    // pass 1: w = exp(leaky(logit)); store; accumulate per-head sums
    float s0 = 0.f, s1 = 0.f, s2 = 0.f, s3 = 0.f;
    for (int i = lane; i < deg; i += 32) {
        int idx = r0 + i;
        int s   = g_csr_src[idx];
        float4 aev = aeL[idx];
        float4 asv = ((const float4*)g_as)[s];
        float a0 = asv.x + adv.x + aev.x;
        float a1 = asv.y + adv.y + aev.y;
        float a2 = asv.z + adv.z + aev.z;
        float a3 = asv.w + adv.w + aev.w;
        a0 = a0 > 0.f ? a0 : 0.2f * a0;
        a1 = a1 > 0.f ? a1 : 0.2f * a1;
        a2 = a2 > 0.f ? a2 : 0.2f * a2;
        a3 = a3 > 0.f ? a3 : 0.2f * a3;
        float w0 = __expf(a0), w1 = __expf(a1), w2 = __expf(a2), w3 = __expf(a3);
        ((float4*)g_w)[idx] = make_float4(w0, w1, w2, w3);
        s0 += w0; s1 += w1; s2 += w2; s3 += w3;
    }
#pragma unroll
    for (int o = 16; o > 0; o >>= 1) {
        s0 += __shfl_xor_sync(~0u, s0, o);
        s1 += __shfl_xor_sync(~0u, s1, o);
        s2 += __shfl_xor_sync(~0u, s2, o);
        s3 += __shfl_xor_sync(~0u, s3, o);
    }
    int head = lane >> 3;
    float hs = (head == 0) ? s0 : (head == 1) ? s1 : (head == 2) ? s2 : s3;
    float hinv = 1.f / (hs + 1e-16f);

    // pass 2: 4x software-pipelined weighted gather
    float4 acc = make_float4(0.f, 0.f, 0.f, 0.f);
    int i = 0;
    for (; i + 4 <= deg; i += 4) {
        int idx = r0 + i;
        int sA = g_csr_src[idx + 0];
        int sB = g_csr_src[idx + 1];
        int sC = g_csr_src[idx + 2];
        int sD = g_csr_src[idx + 3];
        float wA = g_w[(idx + 0) * 4 + head];
        float wB = g_w[(idx + 1) * 4 + head];
        float wC = g_w[(idx + 2) * 4 + head];
        float wD = g_w[(idx + 3) * 4 + head];
        float4 vA = ((const float4*)g_xl)[sA * 32 + lane];
        float4 vB = ((const float4*)g_xl)[sB * 32 + lane];
        float4 vC = ((const float4*)g_xl)[sC * 32 + lane];
        float4 vD = ((const float4*)g_xl)[sD * 32 + lane];
        acc.x = fmaf(wA, vA.x, acc.x); acc.y = fmaf(wA, vA.y, acc.y);
        acc.z = fmaf(wA, vA.z, acc.z); acc.w = fmaf(wA, vA.w, acc.w);
        acc.x = fmaf(wB, vB.x, acc.x); acc.y = fmaf(wB, vB.y, acc.y);
        acc.z = fmaf(wB, vB.z, acc.z); acc.w = fmaf(wB, vB.w, acc.w);
        acc.x = fmaf(wC, vC.x, acc.x); acc.y = fmaf(wC, vC.y, acc.y);
        acc.z = fmaf(wC, vC.z, acc.z); acc.w = fmaf(wC, vC.w, acc.w);
        acc.x = fmaf(wD, vD.x, acc.x); acc.y = fmaf(wD, vD.y, acc.y);
        acc.z = fmaf(wD, vD.z, acc.z); acc.w = fmaf(wD, vD.w, acc.w);
    }
    for (; i < deg; i++) {
        int idx = r0 + i;
        int s = g_csr_src[idx];
        float wgt = g_w[idx * 4 + head];
        float4 v = ((const float4*)g_xl)[s * 32 + lane];
        acc.x = fmaf(wgt, v.x, acc.x);
        acc.y = fmaf(wgt, v.y, acc.y);
        acc.z = fmaf(wgt, v.z, acc.z);
        acc.w = fmaf(wgt, v.w, acc.w);
    }
    float4 bv = ((const float4*)bias)[lane];
    acc.x = fmaf(acc.x, hinv, bv.x);
    acc.y = fmaf(acc.y, hinv, bv.y);
    acc.z = fmaf(acc.z, hinv, bv.z);
    acc.w = fmaf(acc.w, hinv, bv.w);
    ((float4*)g_agg)[gw * 32 + lane] = acc;
}

// ---------------- batchnorm stats ----------------
__global__ void bnp_kernel() {
    int c = threadIdx.x, b = blockIdx.x;
    int rs = b * 391, re = rs + 391; if (re > Nn) re = Nn;
    float s = 0.f, q = 0.f;
    for (int r = rs; r < re; r++) {
        float v = g_agg[r * 128 + c];
        s += v; q = fmaf(v, v, q);
    }
    g_psum[b * 128 + c] = s;
    g_psq[b * 128 + c]  = q;
}
__global__ void bnf_kernel(const float* __restrict__ gamma, const float* __restrict__ beta) {
    int c = threadIdx.x;
    float s = 0.f, q = 0.f;
    for (int b = 0; b < 256; b++) { s += g_psum[b * 128 + c]; q += g_psq[b * 128 + c]; }
    float mu  = s * (1.f / Nn);
    float var = q * (1.f / Nn) - mu * mu;
    float A = gamma[c] * rsqrtf(var + 1e-5f);
    g_bnA[c] = A;
    g_bnB[c] = beta[c] - mu * A;
}

// ---------------- pool (+fused last-layer BN/ReLU) + FC ----------------
__global__ void pool_kernel(const float* __restrict__ fcW, const float* __restrict__ fcb,
                            float* __restrict__ out) {
    __shared__ float sh0[128], sh1[128];
    int g = blockIdx.x, c = threadIdx.x;
    int rs = g_gptr[g], re = g_gptr[g + 1];
    float A = g_bnA[c], B = g_bnB[c];
    float s = 0.f;
    for (int r = rs; r < re; r++)
        s += fmaxf(fmaf(g_agg[r * 128 + c], A, B), 0.f);
    float pooled = s / fmaxf((float)(re - rs), 1.0f);
    sh0[c] = pooled * fcW[c * 2 + 0];
    sh1[c] = pooled * fcW[c * 2 + 1];
    __syncthreads();
    for (int st = 64; st > 0; st >>= 1) {
        if (c < st) { sh0[c] += sh0[c + st]; sh1[c] += sh1[c + st]; }
        __syncthreads();
    }
    if (c == 0) {
        out[g * 2 + 0] = sh0[0] + fcb[0];
        out[g * 2 + 1] = sh1[0] + fcb[1];
    }
}

// ---------------- launcher ----------------
extern "C" void kernel_launch(void* const* d_in, const int* in_sizes, int n_in,
                              void* d_out, int out_size) {
    const float* x      = (const float*)d_in[0];
    const void*  ei     = d_in[1];
    const float* eattr  = (const float*)d_in[2];
    const void*  batchp = d_in[3];
    const float* efcW   = (const float*)d_in[4];
    const float* efcb   = (const float*)d_in[5];
    const float* Ws     = (const float*)d_in[6];
    const float* attS   = (const float*)d_in[7];
    const float* attD   = (const float*)d_in[8];
    const float* attE   = (const float*)d_in[9];
    const float* linE   = (const float*)d_in[10];
    const float* biases = (const float*)d_in[11];
    const float* gamma  = (const float*)d_in[12];
    const float* beta   = (const float*)d_in[13];
    const float* fcW    = (const float*)d_in[14];
    const float* fcb    = (const float*)d_in[15];
    float* out = (float*)d_out;

    zero_kernel<<<391, 256>>>();
    detect_kernel<<<1, 256>>>((const unsigned int*)ei);
    detect2_kernel<<<1, 256>>>((const unsigned int*)batchp);
    conv_edge_kernel<<<3125, 256>>>(ei);
    conv_batch_kernel<<<391, 256>>>(batchp);
    scan1_kernel<<<98, 1024>>>();
    scan2_kernel<<<1, 1>>>();
    scan3_kernel<<<98, 1024>>>();
    bscan_kernel<<<1, 256>>>();
    csr_kernel<<<3125, 256>>>();
    prep_kernel<<<1, 384>>>(linE, attE, efcW, efcb);
    aek_kernel<<<3125, 256>>>(eattr);

    for (int l = 0; l < 3; l++) {
        gemm_tc<<<782, 256>>>(x, Ws + l * 16384, l > 0, attS + l * 128, attD + l * 128);
        agg_kernel<<<12500, 256>>>(l, biases + l * 128);
        bnp_kernel<<<256, 128>>>();
        bnf_kernel<<<1, 128>>>(gamma + l * 128, beta + l * 128);
    }
    pool_kernel<<<Gg, 128>>>(fcW, fcb, out);
}